// round 6
// baseline (speedup 1.0000x reference)
#include <cuda_runtime.h>
#include <cuda_fp16.h>
#include <cstdint>
#include <cstddef>

// ---------------------------------------------------------------------------
// LSTM cell on base-sm_103 ISA (no tcgen05 in this toolchain's PTX target):
// fp16 2-term split (x = hi + lo), 3-pass mma.sync GEMM
// (hi*hi + hi*lo + lo*hi), fused LSTM epilogue via smem restage.
// CTA tile M=128 x N=256 (64 h-cols x 4 gates), warp tile 64x64, 8 warps.
// Round-5 fix: clamp nonlinearity args (inf/inf -> NaN in fast-math tanh).
// ---------------------------------------------------------------------------

#define B_DIM   16384
#define K_TOT   2048        // I + H concatenated
#define N_TOT   4096        // 4*H
#define H_DIM   1024
#define KC      32          // k elems per stage
#define NITER   192         // 3 passes * (2048/32)
#define STAGES  4
#define NTHREADS 256

#define ROW_HALVES 40       // 32 data + 8 pad (80B rows: conflict-free)
#define ROW_BYTES  80
#define STAGE_A    10240    // 128 rows * 80B
#define STAGE_BYTES 30720   // + 256 rows * 80B
#define G_STRIDE   260      // epilogue fp32 tile stride
#define SMEM_BYTES 133120   // max(4*30720, 128*260*4)

// scratch (device globals; no runtime allocation allowed)
__device__ __align__(256) __half g_Ahi[(size_t)B_DIM * K_TOT];
__device__ __align__(256) __half g_Alo[(size_t)B_DIM * K_TOT];
__device__ __align__(256) __half g_Bhi[(size_t)N_TOT * K_TOT];
__device__ __align__(256) __half g_Blo[(size_t)N_TOT * K_TOT];

// ---------------- helpers ----------------
__device__ __forceinline__ uint32_t smem_u32(const void* p) {
    uint32_t a;
    asm("{ .reg .u64 t; cvta.to.shared.u64 t, %1; cvt.u32.u64 %0, t; }"
        : "=r"(a) : "l"(p));
    return a;
}
__device__ __forceinline__ void cp16(uint32_t dst, const void* src) {
    asm volatile("cp.async.cg.shared.global [%0], [%1], 16;" :: "r"(dst), "l"(src));
}
// clamped fast sigmoid/tanh: without the clamp, |g| ~ N(0, 45^2) exceeds 88
// and __expf overflows to inf -> (1-inf)/(1+inf) = NaN via __fdividef.
__device__ __forceinline__ float fsigm(float x) {
    x = fminf(fmaxf(x, -30.0f), 30.0f);
    float e = __expf(-x);
    return __fdividef(1.0f, 1.0f + e);
}
__device__ __forceinline__ float ftanh(float x) {
    x = fminf(fmaxf(x, -15.0f), 15.0f);      // tanh(+-15) == +-1 in fp32
    float e = __expf(-2.0f * x);
    return __fdividef(1.0f - e, 1.0f + e);
}

// ---------------- conversion prepass (fp32 -> fp16 hi/lo) ----------------
__global__ void cvt_A_kernel(const float* __restrict__ inp, const float* __restrict__ hp) {
    const size_t npair = (size_t)B_DIM * K_TOT / 2;
    for (size_t i = (size_t)blockIdx.x * blockDim.x + threadIdx.x;
         i < npair; i += (size_t)gridDim.x * blockDim.x) {
        size_t e = i * 2;
        int col = (int)(e & (K_TOT - 1));
        size_t r = e >> 11;
        const float* src = (col < H_DIM) ? (inp + (r << 10) + col)
                                         : (hp  + (r << 10) + (col - H_DIM));
        float2 v = *(const float2*)src;
        __half hx = __float2half_rn(v.x), hy = __float2half_rn(v.y);
        float lx = v.x - __half2float(hx);
        float ly = v.y - __half2float(hy);
        *(__half2*)(g_Ahi + e) = __halves2half2(hx, hy);
        *(__half2*)(g_Alo + e) = __halves2half2(__float2half_rn(lx), __float2half_rn(ly));
    }
}
__global__ void cvt_B_kernel(const float* __restrict__ wih, const float* __restrict__ whh) {
    const size_t npair = (size_t)N_TOT * K_TOT / 2;
    for (size_t i = (size_t)blockIdx.x * blockDim.x + threadIdx.x;
         i < npair; i += (size_t)gridDim.x * blockDim.x) {
        size_t e = i * 2;
        int col = (int)(e & (K_TOT - 1));
        size_t r = e >> 11;
        const float* src = (col < H_DIM) ? (wih + (r << 10) + col)
                                         : (whh + (r << 10) + (col - H_DIM));
        float2 v = *(const float2*)src;
        __half hx = __float2half_rn(v.x), hy = __float2half_rn(v.y);
        float lx = v.x - __half2float(hx);
        float ly = v.y - __half2float(hy);
        *(__half2*)(g_Bhi + e) = __halves2half2(hx, hy);
        *(__half2*)(g_Blo + e) = __halves2half2(__float2half_rn(lx), __float2half_rn(ly));
    }
}

// ---------------- main fused GEMM + LSTM kernel ----------------
__global__ void __launch_bounds__(NTHREADS, 1)
lstm_mma_kernel(const float* __restrict__ c_prev,
                const float* __restrict__ b_ih, const float* __restrict__ b_hh,
                float* __restrict__ out)
{
    extern __shared__ char smem[];
    const int tid  = threadIdx.x;
    const int lane = tid & 31, wid = tid >> 5;
    const int wr = wid >> 2, wc = wid & 3;       // warp 2x4 grid (m,n)
    const int m0 = blockIdx.y * 128;
    const int h0 = blockIdx.x * 64;
    const uint32_t sb = smem_u32(smem);

    float acc[4][8][4];
    #pragma unroll
    for (int a = 0; a < 4; a++)
        #pragma unroll
        for (int b = 0; b < 8; b++)
            #pragma unroll
            for (int c = 0; c < 4; c++) acc[a][b][c] = 0.0f;

    auto issue_stage = [&](int it) {
        const int pass = it >> 6;
        const int kc   = (it & 63) * KC;
        const __half* Ap = (pass == 2) ? g_Alo : g_Ahi;
        const __half* Bp = (pass == 1) ? g_Blo : g_Bhi;
        const uint32_t st = sb + (uint32_t)(it & (STAGES - 1)) * STAGE_BYTES;
        // A: 128 rows x 32k, 512 cp16 / 256 threads = 2 each
        #pragma unroll
        for (int i = 0; i < 2; i++) {
            int v = tid + i * NTHREADS;
            int r = v >> 2, seg = v & 3;
            cp16(st + (uint32_t)(r * ROW_BYTES + seg * 16),
                 Ap + (size_t)(m0 + r) * K_TOT + kc + seg * 8);
        }
        // B: 256 gathered gate rows x 32k, 1024 cp16 / 256 = 4 each
        #pragma unroll
        for (int i = 0; i < 4; i++) {
            int v = tid + i * NTHREADS;
            int r = v >> 2, seg = v & 3;
            int n = ((r >> 6) << 10) + h0 + (r & 63);   // gate*1024 + h
            cp16(st + STAGE_A + (uint32_t)(r * ROW_BYTES + seg * 16),
                 Bp + (size_t)n * K_TOT + kc + seg * 8);
        }
        asm volatile("cp.async.commit_group;" ::: "memory");
    };

    // prologue: 3 stages in flight
    issue_stage(0); issue_stage(1); issue_stage(2);

    for (int it = 0; it < NITER; it++) {
        asm volatile("cp.async.wait_group 2;" ::: "memory");
        __syncthreads();
        if (it + 3 < NITER) issue_stage(it + 3);
        else asm volatile("cp.async.commit_group;" ::: "memory");

        const uint32_t st = sb + (uint32_t)(it & (STAGES - 1)) * STAGE_BYTES;
        #pragma unroll
        for (int ks = 0; ks < 2; ks++) {
            uint32_t a[4][4], b[8][2];
            #pragma unroll
            for (int mi = 0; mi < 4; mi++) {
                int row  = wr * 64 + mi * 16 + (lane & 15);
                int colb = (ks * 16 + ((lane >> 4) << 3)) * 2;
                uint32_t addr = st + (uint32_t)(row * ROW_BYTES + colb);
                asm volatile("ldmatrix.sync.aligned.m8n8.x4.shared.b16 {%0,%1,%2,%3}, [%4];"
                    : "=r"(a[mi][0]), "=r"(a[mi][1]), "=r"(a[mi][2]), "=r"(a[mi][3])
                    : "r"(addr));
            }
            #pragma unroll
            for (int nj = 0; nj < 8; nj++) {
                int nr = wc * 64 + nj * 8 + (lane >> 2);
                uint32_t addr = st + STAGE_A
                              + (uint32_t)(nr * ROW_BYTES + (ks * 16 + (lane & 3) * 2) * 2);
                asm volatile("ld.shared.b32 %0, [%1];" : "=r"(b[nj][0]) : "r"(addr));
                asm volatile("ld.shared.b32 %0, [%1];" : "=r"(b[nj][1]) : "r"(addr + 16));
            }
            #pragma unroll
            for (int mi = 0; mi < 4; mi++)
                #pragma unroll
                for (int nj = 0; nj < 8; nj++)
                    asm volatile(
                        "mma.sync.aligned.m16n8k16.row.col.f32.f16.f16.f32 "
                        "{%0,%1,%2,%3}, {%4,%5,%6,%7}, {%8,%9}, {%0,%1,%2,%3};"
                        : "+f"(acc[mi][nj][0]), "+f"(acc[mi][nj][1]),
                          "+f"(acc[mi][nj][2]), "+f"(acc[mi][nj][3])
                        : "r"(a[mi][0]), "r"(a[mi][1]), "r"(a[mi][2]), "r"(a[mi][3]),
                          "r"(b[nj][0]), "r"(b[nj][1]));
        }
    }

    // ---- epilogue: restage gates through smem, fused LSTM math ----
    __syncthreads();
    float* g = (float*)smem;
    #pragma unroll
    for (int mi = 0; mi < 4; mi++) {
        int row = wr * 64 + mi * 16 + (lane >> 2);
        #pragma unroll
        for (int nj = 0; nj < 8; nj++) {
            int col = wc * 64 + nj * 8 + (lane & 3) * 2;
            *(float2*)&g[row * G_STRIDE + col] =
                make_float2(acc[mi][nj][0], acc[mi][nj][1]);
            *(float2*)&g[(row + 8) * G_STRIDE + col] =
                make_float2(acc[mi][nj][2], acc[mi][nj][3]);
        }
    }
    __syncthreads();

    for (int idx = tid; idx < 128 * 64; idx += NTHREADS) {
        int m  = idx >> 6, hh = idx & 63;
        int hg = h0 + hh;
        size_t mg = (size_t)(m0 + m);
        float gi = g[m * G_STRIDE + hh]       + b_ih[hg]        + b_hh[hg];
        float gf = g[m * G_STRIDE + 64 + hh]  + b_ih[1024 + hg] + b_hh[1024 + hg];
        float gc = g[m * G_STRIDE + 128 + hh] + b_ih[2048 + hg] + b_hh[2048 + hg];
        float go = g[m * G_STRIDE + 192 + hh] + b_ih[3072 + hg] + b_hh[3072 + hg];
        float ig = fsigm(gi), fg = fsigm(gf), og = fsigm(go);
        float cd = ftanh(gc);
        float cn = c_prev[mg * H_DIM + hg] * fg + ig * cd;
        float hn = ftanh(cn) * og;
        out[mg * H_DIM + hg] = hn;
        out[(size_t)B_DIM * H_DIM + mg * H_DIM + hg] = cn;
    }
}

// ---------------- launch ----------------
extern "C" void kernel_launch(void* const* d_in, const int* in_sizes, int n_in,
                              void* d_out, int out_size) {
    const float* input  = (const float*)d_in[0];
    const float* h_prev = (const float*)d_in[1];
    const float* c_prev = (const float*)d_in[2];
    const float* W_ih   = (const float*)d_in[3];
    const float* W_hh   = (const float*)d_in[4];
    const float* b_ih   = (const float*)d_in[5];
    const float* b_hh   = (const float*)d_in[6];
    float* out = (float*)d_out;

    cvt_A_kernel<<<8192, 256>>>(input, h_prev);
    cvt_B_kernel<<<2048, 256>>>(W_ih, W_hh);

    cudaFuncSetAttribute(lstm_mma_kernel,
                         cudaFuncAttributeMaxDynamicSharedMemorySize, SMEM_BYTES);
    dim3 grid(16, 128);   // 16 h-groups x 128 m-tiles
    lstm_mma_kernel<<<grid, NTHREADS, SMEM_BYTES>>>(c_prev, b_ih, b_hh, out);
}

// round 10
// speedup vs baseline: 1.0010x; 1.0010x over previous
#include <cuda_runtime.h>
#include <cuda_fp16.h>
#include <cstdint>
#include <cstddef>

// ---------------------------------------------------------------------------
// LSTM cell on base-sm_103 ISA (no tcgen05 in this toolchain's PTX target):
// fp16 2-term split (x = hi + lo), 3-pass mma.sync GEMM
// (hi*hi + hi*lo + lo*hi), fused LSTM epilogue via smem restage.
// CTA tile M=128 x N=256 (64 h-cols x 4 gates), warp tile 64x64, 8 warps.
// Round-5 fix: clamp nonlinearity args (inf/inf -> NaN in fast-math tanh).
// ---------------------------------------------------------------------------

#define B_DIM   16384
#define K_TOT   2048        // I + H concatenated
#define N_TOT   4096        // 4*H
#define H_DIM   1024
#define KC      32          // k elems per stage
#define NITER   192         // 3 passes * (2048/32)
#define STAGES  4
#define NTHREADS 256

#define ROW_HALVES 40       // 32 data + 8 pad (80B rows: conflict-free)
#define ROW_BYTES  80
#define STAGE_A    10240    // 128 rows * 80B
#define STAGE_BYTES 30720   // + 256 rows * 80B
#define G_STRIDE   260      // epilogue fp32 tile stride
#define SMEM_BYTES 133120   // max(4*30720, 128*260*4)

// scratch (device globals; no runtime allocation allowed)
__device__ __align__(256) __half g_Ahi[(size_t)B_DIM * K_TOT];
__device__ __align__(256) __half g_Alo[(size_t)B_DIM * K_TOT];
__device__ __align__(256) __half g_Bhi[(size_t)N_TOT * K_TOT];
__device__ __align__(256) __half g_Blo[(size_t)N_TOT * K_TOT];

// ---------------- helpers ----------------
__device__ __forceinline__ uint32_t smem_u32(const void* p) {
    uint32_t a;
    asm("{ .reg .u64 t; cvta.to.shared.u64 t, %1; cvt.u32.u64 %0, t; }"
        : "=r"(a) : "l"(p));
    return a;
}
__device__ __forceinline__ void cp16(uint32_t dst, const void* src) {
    asm volatile("cp.async.cg.shared.global [%0], [%1], 16;" :: "r"(dst), "l"(src));
}
// clamped fast sigmoid/tanh: without the clamp, |g| ~ N(0, 45^2) exceeds 88
// and __expf overflows to inf -> (1-inf)/(1+inf) = NaN via __fdividef.
__device__ __forceinline__ float fsigm(float x) {
    x = fminf(fmaxf(x, -30.0f), 30.0f);
    float e = __expf(-x);
    return __fdividef(1.0f, 1.0f + e);
}
__device__ __forceinline__ float ftanh(float x) {
    x = fminf(fmaxf(x, -15.0f), 15.0f);      // tanh(+-15) == +-1 in fp32
    float e = __expf(-2.0f * x);
    return __fdividef(1.0f - e, 1.0f + e);
}

// ---------------- conversion prepass (fp32 -> fp16 hi/lo) ----------------
__global__ void cvt_A_kernel(const float* __restrict__ inp, const float* __restrict__ hp) {
    const size_t npair = (size_t)B_DIM * K_TOT / 2;
    for (size_t i = (size_t)blockIdx.x * blockDim.x + threadIdx.x;
         i < npair; i += (size_t)gridDim.x * blockDim.x) {
        size_t e = i * 2;
        int col = (int)(e & (K_TOT - 1));
        size_t r = e >> 11;
        const float* src = (col < H_DIM) ? (inp + (r << 10) + col)
                                         : (hp  + (r << 10) + (col - H_DIM));
        float2 v = *(const float2*)src;
        __half hx = __float2half_rn(v.x), hy = __float2half_rn(v.y);
        float lx = v.x - __half2float(hx);
        float ly = v.y - __half2float(hy);
        *(__half2*)(g_Ahi + e) = __halves2half2(hx, hy);
        *(__half2*)(g_Alo + e) = __halves2half2(__float2half_rn(lx), __float2half_rn(ly));
    }
}
__global__ void cvt_B_kernel(const float* __restrict__ wih, const float* __restrict__ whh) {
    const size_t npair = (size_t)N_TOT * K_TOT / 2;
    for (size_t i = (size_t)blockIdx.x * blockDim.x + threadIdx.x;
         i < npair; i += (size_t)gridDim.x * blockDim.x) {
        size_t e = i * 2;
        int col = (int)(e & (K_TOT - 1));
        size_t r = e >> 11;
        const float* src = (col < H_DIM) ? (wih + (r << 10) + col)
                                         : (whh + (r << 10) + (col - H_DIM));
        float2 v = *(const float2*)src;
        __half hx = __float2half_rn(v.x), hy = __float2half_rn(v.y);
        float lx = v.x - __half2float(hx);
        float ly = v.y - __half2float(hy);
        *(__half2*)(g_Bhi + e) = __halves2half2(hx, hy);
        *(__half2*)(g_Blo + e) = __halves2half2(__float2half_rn(lx), __float2half_rn(ly));
    }
}

// ---------------- main fused GEMM + LSTM kernel ----------------
__global__ void __launch_bounds__(NTHREADS, 1)
lstm_mma_kernel(const float* __restrict__ c_prev,
                const float* __restrict__ b_ih, const float* __restrict__ b_hh,
                float* __restrict__ out)
{
    extern __shared__ char smem[];
    const int tid  = threadIdx.x;
    const int lane = tid & 31, wid = tid >> 5;
    const int wr = wid >> 2, wc = wid & 3;       // warp 2x4 grid (m,n)
    const int m0 = blockIdx.y * 128;
    const int h0 = blockIdx.x * 64;
    const uint32_t sb = smem_u32(smem);

    float acc[4][8][4];
    #pragma unroll
    for (int a = 0; a < 4; a++)
        #pragma unroll
        for (int b = 0; b < 8; b++)
            #pragma unroll
            for (int c = 0; c < 4; c++) acc[a][b][c] = 0.0f;

    auto issue_stage = [&](int it) {
        const int pass = it >> 6;
        const int kc   = (it & 63) * KC;
        const __half* Ap = (pass == 2) ? g_Alo : g_Ahi;
        const __half* Bp = (pass == 1) ? g_Blo : g_Bhi;
        const uint32_t st = sb + (uint32_t)(it & (STAGES - 1)) * STAGE_BYTES;
        // A: 128 rows x 32k, 512 cp16 / 256 threads = 2 each
        #pragma unroll
        for (int i = 0; i < 2; i++) {
            int v = tid + i * NTHREADS;
            int r = v >> 2, seg = v & 3;
            cp16(st + (uint32_t)(r * ROW_BYTES + seg * 16),
                 Ap + (size_t)(m0 + r) * K_TOT + kc + seg * 8);
        }
        // B: 256 gathered gate rows x 32k, 1024 cp16 / 256 = 4 each
        #pragma unroll
        for (int i = 0; i < 4; i++) {
            int v = tid + i * NTHREADS;
            int r = v >> 2, seg = v & 3;
            int n = ((r >> 6) << 10) + h0 + (r & 63);   // gate*1024 + h
            cp16(st + STAGE_A + (uint32_t)(r * ROW_BYTES + seg * 16),
                 Bp + (size_t)n * K_TOT + kc + seg * 8);
        }
        asm volatile("cp.async.commit_group;" ::: "memory");
    };

    // prologue: 3 stages in flight
    issue_stage(0); issue_stage(1); issue_stage(2);

    for (int it = 0; it < NITER; it++) {
        asm volatile("cp.async.wait_group 2;" ::: "memory");
        __syncthreads();
        if (it + 3 < NITER) issue_stage(it + 3);
        else asm volatile("cp.async.commit_group;" ::: "memory");

        const uint32_t st = sb + (uint32_t)(it & (STAGES - 1)) * STAGE_BYTES;
        #pragma unroll
        for (int ks = 0; ks < 2; ks++) {
            uint32_t a[4][4], b[8][2];
            #pragma unroll
            for (int mi = 0; mi < 4; mi++) {
                int row  = wr * 64 + mi * 16 + (lane & 15);
                int colb = (ks * 16 + ((lane >> 4) << 3)) * 2;
                uint32_t addr = st + (uint32_t)(row * ROW_BYTES + colb);
                asm volatile("ldmatrix.sync.aligned.m8n8.x4.shared.b16 {%0,%1,%2,%3}, [%4];"
                    : "=r"(a[mi][0]), "=r"(a[mi][1]), "=r"(a[mi][2]), "=r"(a[mi][3])
                    : "r"(addr));
            }
            #pragma unroll
            for (int nj = 0; nj < 8; nj++) {
                int nr = wc * 64 + nj * 8 + (lane >> 2);
                uint32_t addr = st + STAGE_A
                              + (uint32_t)(nr * ROW_BYTES + (ks * 16 + (lane & 3) * 2) * 2);
                asm volatile("ld.shared.b32 %0, [%1];" : "=r"(b[nj][0]) : "r"(addr));
                asm volatile("ld.shared.b32 %0, [%1];" : "=r"(b[nj][1]) : "r"(addr + 16));
            }
            #pragma unroll
            for (int mi = 0; mi < 4; mi++)
                #pragma unroll
                for (int nj = 0; nj < 8; nj++)
                    asm volatile(
                        "mma.sync.aligned.m16n8k16.row.col.f32.f16.f16.f32 "
                        "{%0,%1,%2,%3}, {%4,%5,%6,%7}, {%8,%9}, {%0,%1,%2,%3};"
                        : "+f"(acc[mi][nj][0]), "+f"(acc[mi][nj][1]),
                          "+f"(acc[mi][nj][2]), "+f"(acc[mi][nj][3])
                        : "r"(a[mi][0]), "r"(a[mi][1]), "r"(a[mi][2]), "r"(a[mi][3]),
                          "r"(b[nj][0]), "r"(b[nj][1]));
        }
    }

    // ---- epilogue: restage gates through smem, fused LSTM math ----
    __syncthreads();
    float* g = (float*)smem;
    #pragma unroll
    for (int mi = 0; mi < 4; mi++) {
        int row = wr * 64 + mi * 16 + (lane >> 2);
        #pragma unroll
        for (int nj = 0; nj < 8; nj++) {
            int col = wc * 64 + nj * 8 + (lane & 3) * 2;
            *(float2*)&g[row * G_STRIDE + col] =
                make_float2(acc[mi][nj][0], acc[mi][nj][1]);
            *(float2*)&g[(row + 8) * G_STRIDE + col] =
                make_float2(acc[mi][nj][2], acc[mi][nj][3]);
        }
    }
    __syncthreads();

    for (int idx = tid; idx < 128 * 64; idx += NTHREADS) {
        int m  = idx >> 6, hh = idx & 63;
        int hg = h0 + hh;
        size_t mg = (size_t)(m0 + m);
        float gi = g[m * G_STRIDE + hh]       + b_ih[hg]        + b_hh[hg];
        float gf = g[m * G_STRIDE + 64 + hh]  + b_ih[1024 + hg] + b_hh[1024 + hg];
        float gc = g[m * G_STRIDE + 128 + hh] + b_ih[2048 + hg] + b_hh[2048 + hg];
        float go = g[m * G_STRIDE + 192 + hh] + b_ih[3072 + hg] + b_hh[3072 + hg];
        float ig = fsigm(gi), fg = fsigm(gf), og = fsigm(go);
        float cd = ftanh(gc);
        float cn = c_prev[mg * H_DIM + hg] * fg + ig * cd;
        float hn = ftanh(cn) * og;
        out[mg * H_DIM + hg] = hn;
        out[(size_t)B_DIM * H_DIM + mg * H_DIM + hg] = cn;
    }
}

// ---------------- launch ----------------
extern "C" void kernel_launch(void* const* d_in, const int* in_sizes, int n_in,
                              void* d_out, int out_size) {
    const float* input  = (const float*)d_in[0];
    const float* h_prev = (const float*)d_in[1];
    const float* c_prev = (const float*)d_in[2];
    const float* W_ih   = (const float*)d_in[3];
    const float* W_hh   = (const float*)d_in[4];
    const float* b_ih   = (const float*)d_in[5];
    const float* b_hh   = (const float*)d_in[6];
    float* out = (float*)d_out;

    cvt_A_kernel<<<8192, 256>>>(input, h_prev);
    cvt_B_kernel<<<2048, 256>>>(W_ih, W_hh);

    cudaFuncSetAttribute(lstm_mma_kernel,
                         cudaFuncAttributeMaxDynamicSharedMemorySize, SMEM_BYTES);
    dim3 grid(16, 128);   // 16 h-groups x 128 m-tiles
    lstm_mma_kernel<<<grid, NTHREADS, SMEM_BYTES>>>(c_prev, b_ih, b_hh, out);
}

// round 14
// speedup vs baseline: 1.3649x; 1.3636x over previous
#include <cuda_runtime.h>
#include <cuda_fp16.h>
#include <cstdint>
#include <cstddef>

// ---------------------------------------------------------------------------
// LSTM cell, base-sm_103 ISA (mma.sync path).
// fp16 2-term split (x = hi + lo), 3 products (hi*hi + lo*hi + hi*lo) done
// PER K-CHUNK with register-cached fragments (combined-pass mainloop):
//   - 4 tiles per stage (Ahi, Alo, Bhi, Blo), K=64 chunk, 2 stages
//   - Ahi/Bhi fragments loaded once from smem, used by 2 products each
// CTA tile M=128 x N=256 (64 h-cols x 4 gates), warp tile 64x64, 8 warps.
// Fused LSTM epilogue via smem restage; clamped fast tanh/sigmoid.
// ---------------------------------------------------------------------------

#define B_DIM   16384
#define K_TOT   2048        // I + H concatenated
#define N_TOT   4096        // 4*H
#define H_DIM   1024
#define KC      64          // k elems per stage
#define NITER   32          // 2048/64
#define NTHREADS 256

#define ROW_BYTES  144      // 128B data + 16B pad (conflict-free ldmatrix/lds)
#define OFF_AHI    0u
#define OFF_ALO    18432u   // 128 rows * 144
#define OFF_BHI    36864u   // + 128 rows * 144
#define OFF_BLO    73728u   // + 256 rows * 144
#define STAGE_BYTES 110592u // + 256 rows * 144
#define G_STRIDE   260      // epilogue fp32 tile stride (128*260*4 = 133120)
#define SMEM_BYTES 221184   // 2 stages

// scratch (device globals; no runtime allocation allowed)
__device__ __align__(256) __half g_Ahi[(size_t)B_DIM * K_TOT];
__device__ __align__(256) __half g_Alo[(size_t)B_DIM * K_TOT];
__device__ __align__(256) __half g_Bhi[(size_t)N_TOT * K_TOT];
__device__ __align__(256) __half g_Blo[(size_t)N_TOT * K_TOT];

// ---------------- helpers ----------------
__device__ __forceinline__ uint32_t smem_u32(const void* p) {
    uint32_t a;
    asm("{ .reg .u64 t; cvta.to.shared.u64 t, %1; cvt.u32.u64 %0, t; }"
        : "=r"(a) : "l"(p));
    return a;
}
__device__ __forceinline__ void cp16(uint32_t dst, const void* src) {
    asm volatile("cp.async.cg.shared.global [%0], [%1], 16;" :: "r"(dst), "l"(src));
}
// clamped fast sigmoid/tanh: |g| ~ N(0,45^2) overflows __expf without clamp.
__device__ __forceinline__ float fsigm(float x) {
    x = fminf(fmaxf(x, -30.0f), 30.0f);
    float e = __expf(-x);
    return __fdividef(1.0f, 1.0f + e);
}
__device__ __forceinline__ float ftanh(float x) {
    x = fminf(fmaxf(x, -15.0f), 15.0f);
    float e = __expf(-2.0f * x);
    return __fdividef(1.0f - e, 1.0f + e);
}

__device__ __forceinline__ void ldm_x4(uint32_t* r, uint32_t addr) {
    asm volatile("ldmatrix.sync.aligned.m8n8.x4.shared.b16 {%0,%1,%2,%3}, [%4];"
        : "=r"(r[0]), "=r"(r[1]), "=r"(r[2]), "=r"(r[3]) : "r"(addr));
}
__device__ __forceinline__ void mma16816(float* d, const uint32_t* a, const uint32_t* b) {
    asm volatile(
        "mma.sync.aligned.m16n8k16.row.col.f32.f16.f16.f32 "
        "{%0,%1,%2,%3}, {%4,%5,%6,%7}, {%8,%9}, {%0,%1,%2,%3};"
        : "+f"(d[0]), "+f"(d[1]), "+f"(d[2]), "+f"(d[3])
        : "r"(a[0]), "r"(a[1]), "r"(a[2]), "r"(a[3]), "r"(b[0]), "r"(b[1]));
}

// ---------------- conversion prepass (fp32 -> fp16 hi/lo) ----------------
__global__ void cvt_A_kernel(const float* __restrict__ inp, const float* __restrict__ hp) {
    const size_t npair = (size_t)B_DIM * K_TOT / 2;
    for (size_t i = (size_t)blockIdx.x * blockDim.x + threadIdx.x;
         i < npair; i += (size_t)gridDim.x * blockDim.x) {
        size_t e = i * 2;
        int col = (int)(e & (K_TOT - 1));
        size_t r = e >> 11;
        const float* src = (col < H_DIM) ? (inp + (r << 10) + col)
                                         : (hp  + (r << 10) + (col - H_DIM));
        float2 v = *(const float2*)src;
        __half hx = __float2half_rn(v.x), hy = __float2half_rn(v.y);
        float lx = v.x - __half2float(hx);
        float ly = v.y - __half2float(hy);
        *(__half2*)(g_Ahi + e) = __halves2half2(hx, hy);
        *(__half2*)(g_Alo + e) = __halves2half2(__float2half_rn(lx), __float2half_rn(ly));
    }
}
__global__ void cvt_B_kernel(const float* __restrict__ wih, const float* __restrict__ whh) {
    const size_t npair = (size_t)N_TOT * K_TOT / 2;
    for (size_t i = (size_t)blockIdx.x * blockDim.x + threadIdx.x;
         i < npair; i += (size_t)gridDim.x * blockDim.x) {
        size_t e = i * 2;
        int col = (int)(e & (K_TOT - 1));
        size_t r = e >> 11;
        const float* src = (col < H_DIM) ? (wih + (r << 10) + col)
                                         : (whh + (r << 10) + (col - H_DIM));
        float2 v = *(const float2*)src;
        __half hx = __float2half_rn(v.x), hy = __float2half_rn(v.y);
        float lx = v.x - __half2float(hx);
        float ly = v.y - __half2float(hy);
        *(__half2*)(g_Bhi + e) = __halves2half2(hx, hy);
        *(__half2*)(g_Blo + e) = __halves2half2(__float2half_rn(lx), __float2half_rn(ly));
    }
}

// ---------------- main fused GEMM + LSTM kernel ----------------
__global__ void __launch_bounds__(NTHREADS, 1)
lstm_mma_kernel(const float* __restrict__ c_prev,
                const float* __restrict__ b_ih, const float* __restrict__ b_hh,
                float* __restrict__ out)
{
    extern __shared__ char smem[];
    const int tid  = threadIdx.x;
    const int lane = tid & 31, wid = tid >> 5;
    const int wr = wid >> 2, wc = wid & 3;       // warp 2x4 grid (m,n)
    const int m0 = blockIdx.y * 128;
    const int h0 = blockIdx.x * 64;
    const uint32_t sb = smem_u32(smem);

    float acc[4][8][4];
    #pragma unroll
    for (int a = 0; a < 4; a++)
        #pragma unroll
        for (int b = 0; b < 8; b++)
            #pragma unroll
            for (int c = 0; c < 4; c++) acc[a][b][c] = 0.0f;

    // stage loader: 4 tiles, K=64 chunk. 6144 cp16 / 256 thr = 24 each.
    auto issue_stage = [&](int it) {
        const int kc = it * KC;
        const uint32_t st = sb + (uint32_t)(it & 1) * STAGE_BYTES;
        // A tiles: 128 rows x 8 segs = 1024 cp16 each (4 per thread)
        #pragma unroll
        for (int i = 0; i < 4; i++) {
            int v = tid + i * NTHREADS;
            int r = v >> 3, seg = v & 7;
            uint32_t d = st + (uint32_t)(r * ROW_BYTES + seg * 16);
            size_t  go = (size_t)(m0 + r) * K_TOT + kc + seg * 8;
            cp16(d + OFF_AHI, g_Ahi + go);
            cp16(d + OFF_ALO, g_Alo + go);
        }
        // B tiles: 256 gathered gate rows x 8 segs = 2048 cp16 each (8 per thread)
        #pragma unroll
        for (int i = 0; i < 8; i++) {
            int v = tid + i * NTHREADS;
            int r = v >> 3, seg = v & 7;
            int n = ((r >> 6) << 10) + h0 + (r & 63);   // gate*1024 + h
            uint32_t d = st + (uint32_t)(r * ROW_BYTES + seg * 16);
            size_t  go = (size_t)n * K_TOT + kc + seg * 8;
            cp16(d + OFF_BHI, g_Bhi + go);
            cp16(d + OFF_BLO, g_Blo + go);
        }
        asm volatile("cp.async.commit_group;" ::: "memory");
    };

    issue_stage(0);
    issue_stage(1);

    for (int it = 0; it < NITER; it++) {
        asm volatile("cp.async.wait_group 1;" ::: "memory");
        __syncthreads();
        const uint32_t st = sb + (uint32_t)(it & 1) * STAGE_BYTES;

        #pragma unroll 1
        for (int ks = 0; ks < 4; ks++) {
            const uint32_t kb = (uint32_t)(ks * 32);   // byte offset of k16 slice
            // --- load Ahi, Bhi fragments (each used by 2 products) ---
            uint32_t ahi[4][4], bhi[8][2];
            #pragma unroll
            for (int mi = 0; mi < 4; mi++) {
                int row = wr * 64 + mi * 16 + (lane & 15);
                ldm_x4(ahi[mi], st + OFF_AHI
                       + (uint32_t)(row * ROW_BYTES) + kb + ((lane >> 4) << 4));
            }
            #pragma unroll
            for (int nj = 0; nj < 8; nj++) {
                int nr = wc * 64 + nj * 8 + (lane >> 2);
                uint32_t addr = st + OFF_BHI
                              + (uint32_t)(nr * ROW_BYTES) + kb + (lane & 3) * 4;
                asm volatile("ld.shared.b32 %0, [%1];" : "=r"(bhi[nj][0]) : "r"(addr));
                asm volatile("ld.shared.b32 %0, [%1];" : "=r"(bhi[nj][1]) : "r"(addr + 16));
            }
            // --- product 1: hi*hi ---
            #pragma unroll
            for (int mi = 0; mi < 4; mi++)
                #pragma unroll
                for (int nj = 0; nj < 8; nj++)
                    mma16816(acc[mi][nj], ahi[mi], bhi[nj]);
            // --- product 2: lo*hi (reuse bhi) ---
            {
                uint32_t alo[4][4];
                #pragma unroll
                for (int mi = 0; mi < 4; mi++) {
                    int row = wr * 64 + mi * 16 + (lane & 15);
                    ldm_x4(alo[mi], st + OFF_ALO
                           + (uint32_t)(row * ROW_BYTES) + kb + ((lane >> 4) << 4));
                }
                #pragma unroll
                for (int mi = 0; mi < 4; mi++)
                    #pragma unroll
                    for (int nj = 0; nj < 8; nj++)
                        mma16816(acc[mi][nj], alo[mi], bhi[nj]);
            }
            // --- product 3: hi*lo (reuse ahi) ---
            {
                uint32_t blo[8][2];
                #pragma unroll
                for (int nj = 0; nj < 8; nj++) {
                    int nr = wc * 64 + nj * 8 + (lane >> 2);
                    uint32_t addr = st + OFF_BLO
                                  + (uint32_t)(nr * ROW_BYTES) + kb + (lane & 3) * 4;
                    asm volatile("ld.shared.b32 %0, [%1];" : "=r"(blo[nj][0]) : "r"(addr));
                    asm volatile("ld.shared.b32 %0, [%1];" : "=r"(blo[nj][1]) : "r"(addr + 16));
                }
                #pragma unroll
                for (int mi = 0; mi < 4; mi++)
                    #pragma unroll
                    for (int nj = 0; nj < 8; nj++)
                        mma16816(acc[mi][nj], ahi[mi], blo[nj]);
            }
        }

        __syncthreads();                 // stage buffer free before refill
        if (it + 2 < NITER) issue_stage(it + 2);
        else asm volatile("cp.async.commit_group;" ::: "memory");
    }

    // ---- epilogue: restage gates through smem, fused LSTM math ----
    __syncthreads();
    float* g = (float*)smem;
    #pragma unroll
    for (int mi = 0; mi < 4; mi++) {
        int row = wr * 64 + mi * 16 + (lane >> 2);
        #pragma unroll
        for (int nj = 0; nj < 8; nj++) {
            int col = wc * 64 + nj * 8 + (lane & 3) * 2;
            *(float2*)&g[row * G_STRIDE + col] =
                make_float2(acc[mi][nj][0], acc[mi][nj][1]);
            *(float2*)&g[(row + 8) * G_STRIDE + col] =
                make_float2(acc[mi][nj][2], acc[mi][nj][3]);
        }
    }
    __syncthreads();

    for (int idx = tid; idx < 128 * 64; idx += NTHREADS) {
        int m  = idx >> 6, hh = idx & 63;
        int hg = h0 + hh;
        size_t mg = (size_t)(m0 + m);
        float gi = g[m * G_STRIDE + hh]       + b_ih[hg]        + b_hh[hg];
        float gf = g[m * G_STRIDE + 64 + hh]  + b_ih[1024 + hg] + b_hh[1024 + hg];
        float gc = g[m * G_STRIDE + 128 + hh] + b_ih[2048 + hg] + b_hh[2048 + hg];
        float go = g[m * G_STRIDE + 192 + hh] + b_ih[3072 + hg] + b_hh[3072 + hg];
        float ig = fsigm(gi), fg = fsigm(gf), og = fsigm(go);
        float cd = ftanh(gc);
        float cn = c_prev[mg * H_DIM + hg] * fg + ig * cd;
        float hn = ftanh(cn) * og;
        out[mg * H_DIM + hg] = hn;
        out[(size_t)B_DIM * H_DIM + mg * H_DIM + hg] = cn;
    }
}

// ---------------- launch ----------------
extern "C" void kernel_launch(void* const* d_in, const int* in_sizes, int n_in,
                              void* d_out, int out_size) {
    const float* input  = (const float*)d_in[0];
    const float* h_prev = (const float*)d_in[1];
    const float* c_prev = (const float*)d_in[2];
    const float* W_ih   = (const float*)d_in[3];
    const float* W_hh   = (const float*)d_in[4];
    const float* b_ih   = (const float*)d_in[5];
    const float* b_hh   = (const float*)d_in[6];
    float* out = (float*)d_out;

    cvt_A_kernel<<<8192, 256>>>(input, h_prev);
    cvt_B_kernel<<<2048, 256>>>(W_ih, W_hh);

    cudaFuncSetAttribute(lstm_mma_kernel,
                         cudaFuncAttributeMaxDynamicSharedMemorySize, SMEM_BYTES);
    dim3 grid(16, 128);   // 16 h-groups x 128 m-tiles
    lstm_mma_kernel<<<grid, NTHREADS, SMEM_BYTES>>>(c_prev, b_ih, b_hh, out);
}

// round 15
// speedup vs baseline: 1.3677x; 1.0020x over previous
#include <cuda_runtime.h>
#include <cuda_fp16.h>
#include <cstdint>
#include <cstddef>

// ---------------------------------------------------------------------------
// LSTM cell, base-sm_103 ISA (mma.sync path).
// fp16 2-term split (x = hi + lo), 3 products (hi*hi + lo*hi + hi*lo) done
// PER K-CHUNK with register-cached fragments (combined-pass mainloop):
//   - 4 tiles per stage (Ahi, Alo, Bhi, Blo), K=64 chunk, 2 stages
//   - Ahi/Bhi fragments loaded once from smem, used by 2 products each
// CTA tile M=128 x N=256 (64 h-cols x 4 gates), warp tile 64x64, 8 warps.
// Fused LSTM epilogue via smem restage; clamped fast tanh/sigmoid.
// ---------------------------------------------------------------------------

#define B_DIM   16384
#define K_TOT   2048        // I + H concatenated
#define N_TOT   4096        // 4*H
#define H_DIM   1024
#define KC      64          // k elems per stage
#define NITER   32          // 2048/64
#define NTHREADS 256

#define ROW_BYTES  144      // 128B data + 16B pad (conflict-free ldmatrix/lds)
#define OFF_AHI    0u
#define OFF_ALO    18432u   // 128 rows * 144
#define OFF_BHI    36864u   // + 128 rows * 144
#define OFF_BLO    73728u   // + 256 rows * 144
#define STAGE_BYTES 110592u // + 256 rows * 144
#define G_STRIDE   260      // epilogue fp32 tile stride (128*260*4 = 133120)
#define SMEM_BYTES 221184   // 2 stages

// scratch (device globals; no runtime allocation allowed)
__device__ __align__(256) __half g_Ahi[(size_t)B_DIM * K_TOT];
__device__ __align__(256) __half g_Alo[(size_t)B_DIM * K_TOT];
__device__ __align__(256) __half g_Bhi[(size_t)N_TOT * K_TOT];
__device__ __align__(256) __half g_Blo[(size_t)N_TOT * K_TOT];

// ---------------- helpers ----------------
__device__ __forceinline__ uint32_t smem_u32(const void* p) {
    uint32_t a;
    asm("{ .reg .u64 t; cvta.to.shared.u64 t, %1; cvt.u32.u64 %0, t; }"
        : "=r"(a) : "l"(p));
    return a;
}
__device__ __forceinline__ void cp16(uint32_t dst, const void* src) {
    asm volatile("cp.async.cg.shared.global [%0], [%1], 16;" :: "r"(dst), "l"(src));
}
// clamped fast sigmoid/tanh: |g| ~ N(0,45^2) overflows __expf without clamp.
__device__ __forceinline__ float fsigm(float x) {
    x = fminf(fmaxf(x, -30.0f), 30.0f);
    float e = __expf(-x);
    return __fdividef(1.0f, 1.0f + e);
}
__device__ __forceinline__ float ftanh(float x) {
    x = fminf(fmaxf(x, -15.0f), 15.0f);
    float e = __expf(-2.0f * x);
    return __fdividef(1.0f - e, 1.0f + e);
}

__device__ __forceinline__ void ldm_x4(uint32_t* r, uint32_t addr) {
    asm volatile("ldmatrix.sync.aligned.m8n8.x4.shared.b16 {%0,%1,%2,%3}, [%4];"
        : "=r"(r[0]), "=r"(r[1]), "=r"(r[2]), "=r"(r[3]) : "r"(addr));
}
__device__ __forceinline__ void mma16816(float* d, const uint32_t* a, const uint32_t* b) {
    asm volatile(
        "mma.sync.aligned.m16n8k16.row.col.f32.f16.f16.f32 "
        "{%0,%1,%2,%3}, {%4,%5,%6,%7}, {%8,%9}, {%0,%1,%2,%3};"
        : "+f"(d[0]), "+f"(d[1]), "+f"(d[2]), "+f"(d[3])
        : "r"(a[0]), "r"(a[1]), "r"(a[2]), "r"(a[3]), "r"(b[0]), "r"(b[1]));
}

// ---------------- conversion prepass (fp32 -> fp16 hi/lo) ----------------
__global__ void cvt_A_kernel(const float* __restrict__ inp, const float* __restrict__ hp) {
    const size_t npair = (size_t)B_DIM * K_TOT / 2;
    for (size_t i = (size_t)blockIdx.x * blockDim.x + threadIdx.x;
         i < npair; i += (size_t)gridDim.x * blockDim.x) {
        size_t e = i * 2;
        int col = (int)(e & (K_TOT - 1));
        size_t r = e >> 11;
        const float* src = (col < H_DIM) ? (inp + (r << 10) + col)
                                         : (hp  + (r << 10) + (col - H_DIM));
        float2 v = *(const float2*)src;
        __half hx = __float2half_rn(v.x), hy = __float2half_rn(v.y);
        float lx = v.x - __half2float(hx);
        float ly = v.y - __half2float(hy);
        *(__half2*)(g_Ahi + e) = __halves2half2(hx, hy);
        *(__half2*)(g_Alo + e) = __halves2half2(__float2half_rn(lx), __float2half_rn(ly));
    }
}
__global__ void cvt_B_kernel(const float* __restrict__ wih, const float* __restrict__ whh) {
    const size_t npair = (size_t)N_TOT * K_TOT / 2;
    for (size_t i = (size_t)blockIdx.x * blockDim.x + threadIdx.x;
         i < npair; i += (size_t)gridDim.x * blockDim.x) {
        size_t e = i * 2;
        int col = (int)(e & (K_TOT - 1));
        size_t r = e >> 11;
        const float* src = (col < H_DIM) ? (wih + (r << 10) + col)
                                         : (whh + (r << 10) + (col - H_DIM));
        float2 v = *(const float2*)src;
        __half hx = __float2half_rn(v.x), hy = __float2half_rn(v.y);
        float lx = v.x - __half2float(hx);
        float ly = v.y - __half2float(hy);
        *(__half2*)(g_Bhi + e) = __halves2half2(hx, hy);
        *(__half2*)(g_Blo + e) = __halves2half2(__float2half_rn(lx), __float2half_rn(ly));
    }
}

// ---------------- main fused GEMM + LSTM kernel ----------------
__global__ void __launch_bounds__(NTHREADS, 1)
lstm_mma_kernel(const float* __restrict__ c_prev,
                const float* __restrict__ b_ih, const float* __restrict__ b_hh,
                float* __restrict__ out)
{
    extern __shared__ char smem[];
    const int tid  = threadIdx.x;
    const int lane = tid & 31, wid = tid >> 5;
    const int wr = wid >> 2, wc = wid & 3;       // warp 2x4 grid (m,n)
    const int m0 = blockIdx.y * 128;
    const int h0 = blockIdx.x * 64;
    const uint32_t sb = smem_u32(smem);

    float acc[4][8][4];
    #pragma unroll
    for (int a = 0; a < 4; a++)
        #pragma unroll
        for (int b = 0; b < 8; b++)
            #pragma unroll
            for (int c = 0; c < 4; c++) acc[a][b][c] = 0.0f;

    // stage loader: 4 tiles, K=64 chunk. 6144 cp16 / 256 thr = 24 each.
    auto issue_stage = [&](int it) {
        const int kc = it * KC;
        const uint32_t st = sb + (uint32_t)(it & 1) * STAGE_BYTES;
        // A tiles: 128 rows x 8 segs = 1024 cp16 each (4 per thread)
        #pragma unroll
        for (int i = 0; i < 4; i++) {
            int v = tid + i * NTHREADS;
            int r = v >> 3, seg = v & 7;
            uint32_t d = st + (uint32_t)(r * ROW_BYTES + seg * 16);
            size_t  go = (size_t)(m0 + r) * K_TOT + kc + seg * 8;
            cp16(d + OFF_AHI, g_Ahi + go);
            cp16(d + OFF_ALO, g_Alo + go);
        }
        // B tiles: 256 gathered gate rows x 8 segs = 2048 cp16 each (8 per thread)
        #pragma unroll
        for (int i = 0; i < 8; i++) {
            int v = tid + i * NTHREADS;
            int r = v >> 3, seg = v & 7;
            int n = ((r >> 6) << 10) + h0 + (r & 63);   // gate*1024 + h
            uint32_t d = st + (uint32_t)(r * ROW_BYTES + seg * 16);
            size_t  go = (size_t)n * K_TOT + kc + seg * 8;
            cp16(d + OFF_BHI, g_Bhi + go);
            cp16(d + OFF_BLO, g_Blo + go);
        }
        asm volatile("cp.async.commit_group;" ::: "memory");
    };

    issue_stage(0);
    issue_stage(1);

    for (int it = 0; it < NITER; it++) {
        asm volatile("cp.async.wait_group 1;" ::: "memory");
        __syncthreads();
        const uint32_t st = sb + (uint32_t)(it & 1) * STAGE_BYTES;

        #pragma unroll 1
        for (int ks = 0; ks < 4; ks++) {
            const uint32_t kb = (uint32_t)(ks * 32);   // byte offset of k16 slice
            // --- load Ahi, Bhi fragments (each used by 2 products) ---
            uint32_t ahi[4][4], bhi[8][2];
            #pragma unroll
            for (int mi = 0; mi < 4; mi++) {
                int row = wr * 64 + mi * 16 + (lane & 15);
                ldm_x4(ahi[mi], st + OFF_AHI
                       + (uint32_t)(row * ROW_BYTES) + kb + ((lane >> 4) << 4));
            }
            #pragma unroll
            for (int nj = 0; nj < 8; nj++) {
                int nr = wc * 64 + nj * 8 + (lane >> 2);
                uint32_t addr = st + OFF_BHI
                              + (uint32_t)(nr * ROW_BYTES) + kb + (lane & 3) * 4;
                asm volatile("ld.shared.b32 %0, [%1];" : "=r"(bhi[nj][0]) : "r"(addr));
                asm volatile("ld.shared.b32 %0, [%1];" : "=r"(bhi[nj][1]) : "r"(addr + 16));
            }
            // --- product 1: hi*hi ---
            #pragma unroll
            for (int mi = 0; mi < 4; mi++)
                #pragma unroll
                for (int nj = 0; nj < 8; nj++)
                    mma16816(acc[mi][nj], ahi[mi], bhi[nj]);
            // --- product 2: lo*hi (reuse bhi) ---
            {
                uint32_t alo[4][4];
                #pragma unroll
                for (int mi = 0; mi < 4; mi++) {
                    int row = wr * 64 + mi * 16 + (lane & 15);
                    ldm_x4(alo[mi], st + OFF_ALO
                           + (uint32_t)(row * ROW_BYTES) + kb + ((lane >> 4) << 4));
                }
                #pragma unroll
                for (int mi = 0; mi < 4; mi++)
                    #pragma unroll
                    for (int nj = 0; nj < 8; nj++)
                        mma16816(acc[mi][nj], alo[mi], bhi[nj]);
            }
            // --- product 3: hi*lo (reuse ahi) ---
            {
                uint32_t blo[8][2];
                #pragma unroll
                for (int nj = 0; nj < 8; nj++) {
                    int nr = wc * 64 + nj * 8 + (lane >> 2);
                    uint32_t addr = st + OFF_BLO
                                  + (uint32_t)(nr * ROW_BYTES) + kb + (lane & 3) * 4;
                    asm volatile("ld.shared.b32 %0, [%1];" : "=r"(blo[nj][0]) : "r"(addr));
                    asm volatile("ld.shared.b32 %0, [%1];" : "=r"(blo[nj][1]) : "r"(addr + 16));
                }
                #pragma unroll
                for (int mi = 0; mi < 4; mi++)
                    #pragma unroll
                    for (int nj = 0; nj < 8; nj++)
                        mma16816(acc[mi][nj], ahi[mi], blo[nj]);
            }
        }

        __syncthreads();                 // stage buffer free before refill
        if (it + 2 < NITER) issue_stage(it + 2);
        else asm volatile("cp.async.commit_group;" ::: "memory");
    }

    // ---- epilogue: restage gates through smem, fused LSTM math ----
    __syncthreads();
    float* g = (float*)smem;
    #pragma unroll
    for (int mi = 0; mi < 4; mi++) {
        int row = wr * 64 + mi * 16 + (lane >> 2);
        #pragma unroll
        for (int nj = 0; nj < 8; nj++) {
            int col = wc * 64 + nj * 8 + (lane & 3) * 2;
            *(float2*)&g[row * G_STRIDE + col] =
                make_float2(acc[mi][nj][0], acc[mi][nj][1]);
            *(float2*)&g[(row + 8) * G_STRIDE + col] =
                make_float2(acc[mi][nj][2], acc[mi][nj][3]);
        }
    }
    __syncthreads();

    for (int idx = tid; idx < 128 * 64; idx += NTHREADS) {
        int m  = idx >> 6, hh = idx & 63;
        int hg = h0 + hh;
        size_t mg = (size_t)(m0 + m);
        float gi = g[m * G_STRIDE + hh]       + b_ih[hg]        + b_hh[hg];
        float gf = g[m * G_STRIDE + 64 + hh]  + b_ih[1024 + hg] + b_hh[1024 + hg];
        float gc = g[m * G_STRIDE + 128 + hh] + b_ih[2048 + hg] + b_hh[2048 + hg];
        float go = g[m * G_STRIDE + 192 + hh] + b_ih[3072 + hg] + b_hh[3072 + hg];
        float ig = fsigm(gi), fg = fsigm(gf), og = fsigm(go);
        float cd = ftanh(gc);
        float cn = c_prev[mg * H_DIM + hg] * fg + ig * cd;
        float hn = ftanh(cn) * og;
        out[mg * H_DIM + hg] = hn;
        out[(size_t)B_DIM * H_DIM + mg * H_DIM + hg] = cn;
    }
}

// ---------------- launch ----------------
extern "C" void kernel_launch(void* const* d_in, const int* in_sizes, int n_in,
                              void* d_out, int out_size) {
    const float* input  = (const float*)d_in[0];
    const float* h_prev = (const float*)d_in[1];
    const float* c_prev = (const float*)d_in[2];
    const float* W_ih   = (const float*)d_in[3];
    const float* W_hh   = (const float*)d_in[4];
    const float* b_ih   = (const float*)d_in[5];
    const float* b_hh   = (const float*)d_in[6];
    float* out = (float*)d_out;

    cvt_A_kernel<<<8192, 256>>>(input, h_prev);
    cvt_B_kernel<<<2048, 256>>>(W_ih, W_hh);

    cudaFuncSetAttribute(lstm_mma_kernel,
                         cudaFuncAttributeMaxDynamicSharedMemorySize, SMEM_BYTES);
    dim3 grid(16, 128);   // 16 h-groups x 128 m-tiles
    lstm_mma_kernel<<<grid, NTHREADS, SMEM_BYTES>>>(c_prev, b_ih, b_hh, out);
}